// round 15
// baseline (speedup 1.0000x reference)
#include <cuda_runtime.h>
#include <math.h>

// ---------------------------------------------------------------------------
// Weighted Kabsch, fully fused single kernel, 17 hot channels:
//   0      : count(w > 0)
//   1      : sum w
//   2..4   : sum w*x
//   5..7   : sum w*y
//   8..16  : sum w*y_o*x_i   (row-major o*3+i)
// The nep (count<3) correction needs unweighted sums; instead of carrying 15
// more channels (which overflows the register budget and spills), the last
// block RE-SCANS the inputs if and only if nep — a correctness-only path that
// never executes for data with any 3 positive weights.
// Tail partial reduction is FP32 (FP64 version cost ~29us on one SM's pipe).
// ---------------------------------------------------------------------------

#define NBLK 1184   // 148 SMs * 8
#define NTHR 256
#define NCH  17
#define STR  32     // g_part row stride (padded)

__device__ float        g_part[NBLK * STR];
__device__ unsigned int g_tick = 0;   // reset by last block each launch

__device__ __forceinline__ float det3f(const float M[3][3]) {
    return M[0][0] * (M[1][1] * M[2][2] - M[1][2] * M[2][1])
         - M[0][1] * (M[1][0] * M[2][2] - M[1][2] * M[2][0])
         + M[0][2] * (M[1][0] * M[2][1] - M[1][1] * M[2][0]);
}

template<int P, int Q>
__device__ __forceinline__ void jrot(float S[3][3], float V[3][3]) {
    float apq = S[P][Q];
    float d2 = 2.0f * apq;
    d2 = (d2 == 0.0f) ? 1e-37f : d2;
    float tau = __fdividef(S[Q][Q] - S[P][P], d2);
    tau = fminf(fmaxf(tau, -1e18f), 1e18f);
    float z  = fmaf(tau, tau, 1.0f);
    float sq = z * rsqrtf(z);                    // sqrt(z), z >= 1
    float t  = __fdividef(1.0f, fabsf(tau) + sq);
    t = copysignf(t, tau);
    float cc = rsqrtf(fmaf(t, t, 1.0f));
    float ss = t * cc;
#pragma unroll
    for (int kk = 0; kk < 3; kk++) {
        float skp = S[kk][P], skq = S[kk][Q];
        S[kk][P] = fmaf(cc, skp, -ss * skq);
        S[kk][Q] = fmaf(ss, skp,  cc * skq);
    }
#pragma unroll
    for (int kk = 0; kk < 3; kk++) {
        float spk = S[P][kk], sqk = S[Q][kk];
        S[P][kk] = fmaf(cc, spk, -ss * sqk);
        S[Q][kk] = fmaf(ss, spk,  cc * sqk);
    }
#pragma unroll
    for (int kk = 0; kk < 3; kk++) {
        float vkp = V[kk][P], vkq = V[kk][Q];
        V[kk][P] = fmaf(cc, vkp, -ss * vkq);
        V[kk][Q] = fmaf(ss, vkp,  cc * vkq);
    }
}

__global__ __launch_bounds__(NTHR) void kabsch_fused_kernel(
    const float4* __restrict__ x4, const float4* __restrict__ y4,
    const float4* __restrict__ w4, int n4,
    float* __restrict__ out, int out_size, float Nf)
{
    // ---------------- Phase 1: streaming, 17 channels ----------------
    float acc[NCH];
#pragma unroll
    for (int i = 0; i < NCH; i++) acc[i] = 0.0f;

    int stride = gridDim.x * blockDim.x;
    for (int g = blockIdx.x * blockDim.x + threadIdx.x; g < n4; g += stride) {
        float4 xa = x4[g * 3 + 0];
        float4 xb = x4[g * 3 + 1];
        float4 xc = x4[g * 3 + 2];
        float4 ya = y4[g * 3 + 0];
        float4 yb = y4[g * 3 + 1];
        float4 yc = y4[g * 3 + 2];
        float4 ww = w4[g];

        float X[4][3] = {{xa.x, xa.y, xa.z}, {xa.w, xb.x, xb.y},
                         {xb.z, xb.w, xc.x}, {xc.y, xc.z, xc.w}};
        float Y[4][3] = {{ya.x, ya.y, ya.z}, {ya.w, yb.x, yb.y},
                         {yb.z, yb.w, yc.x}, {yc.y, yc.z, yc.w}};
        float Wp[4] = {ww.x, ww.y, ww.z, ww.w};

#pragma unroll
        for (int p = 0; p < 4; p++) {
            float w = Wp[p];
            acc[0] += (w > 0.0f) ? 1.0f : 0.0f;
            acc[1] += w;
            float wy0 = w * Y[p][0];
            float wy1 = w * Y[p][1];
            float wy2 = w * Y[p][2];
            acc[2] = fmaf(w, X[p][0], acc[2]);
            acc[3] = fmaf(w, X[p][1], acc[3]);
            acc[4] = fmaf(w, X[p][2], acc[4]);
            acc[5] += wy0;
            acc[6] += wy1;
            acc[7] += wy2;
            acc[8]  = fmaf(wy0, X[p][0], acc[8]);
            acc[9]  = fmaf(wy0, X[p][1], acc[9]);
            acc[10] = fmaf(wy0, X[p][2], acc[10]);
            acc[11] = fmaf(wy1, X[p][0], acc[11]);
            acc[12] = fmaf(wy1, X[p][1], acc[12]);
            acc[13] = fmaf(wy1, X[p][2], acc[13]);
            acc[14] = fmaf(wy2, X[p][0], acc[14]);
            acc[15] = fmaf(wy2, X[p][1], acc[15]);
            acc[16] = fmaf(wy2, X[p][2], acc[16]);
        }
    }

    // warp tree reduction per channel
#pragma unroll
    for (int i = 0; i < NCH; i++) {
        float v = acc[i];
        for (int off = 16; off; off >>= 1)
            v += __shfl_down_sync(0xffffffffu, v, off);
        acc[i] = v;
    }

    __shared__ float sh[NTHR / 32][NCH];
    int tid  = threadIdx.x;
    int lane = tid & 31;
    int warp = tid >> 5;
    if (lane == 0) {
#pragma unroll
        for (int i = 0; i < NCH; i++) sh[warp][i] = acc[i];
    }
    __syncthreads();

    if (tid < NCH) {
        float v = 0.0f;
#pragma unroll
        for (int wp = 0; wp < NTHR / 32; wp++) v += sh[wp][tid];
        g_part[blockIdx.x * STR + tid] = v;
    }

    // ---------------- Arrival: last-block detection ----------------
    __threadfence();
    __syncthreads();
    __shared__ int s_last;
    if (tid == 0) {
        unsigned int old = atomicAdd(&g_tick, 1u);
        s_last = (old == NBLK - 1) ? 1 : 0;
    }
    __syncthreads();
    if (!s_last) return;

    // ---------------- Phase 2: fp32 partial reduction (last block) --------
    if (tid == 0) g_tick = 0;

    __shared__ float  s2[8][NCH];
    __shared__ double sums[NCH];
    {
        int c = tid & 31;
        int k = tid >> 5;                // 8 chunks of 148 blocks
        const int per = NBLK / 8;        // 148 = 4*37
        if (c < NCH) {
            const float* base = &g_part[((k * per) << 5) + c];
            float a0 = 0.0f, a1 = 0.0f, a2 = 0.0f, a3 = 0.0f;
#pragma unroll
            for (int j = 0; j < per / 4; j++) {
                a0 += base[((4 * j + 0) << 5)];
                a1 += base[((4 * j + 1) << 5)];
                a2 += base[((4 * j + 2) << 5)];
                a3 += base[((4 * j + 3) << 5)];
            }
            s2[k][c] = (a0 + a1) + (a2 + a3);
        }
    }
    __syncthreads();
    if (tid < NCH) {
        double t = 0.0;
#pragma unroll
        for (int kk = 0; kk < 8; kk++) t += (double)s2[kk][tid];
        sums[tid] = t;
    }
    __syncthreads();

    // ------- nep rescue: block-wide rescan for unweighted sums (rare) -----
    __shared__ int s_nep;
    __shared__ double ex[15];   // 0..2 Σx, 3..5 Σy, 6..14 Σ y_o x_i
    if (tid == 0) s_nep = (sums[0] < 2.5) ? 1 : 0;
    __syncthreads();
    if (s_nep) {
        // correctness-only path: requires all but <=2 of N weights <= 0.
        double a[15];
#pragma unroll
        for (int i = 0; i < 15; i++) a[i] = 0.0;
        for (int g = tid; g < n4; g += NTHR) {
            float4 xa = x4[g * 3 + 0];
            float4 xb = x4[g * 3 + 1];
            float4 xc = x4[g * 3 + 2];
            float4 ya = y4[g * 3 + 0];
            float4 yb = y4[g * 3 + 1];
            float4 yc = y4[g * 3 + 2];
            float X[4][3] = {{xa.x, xa.y, xa.z}, {xa.w, xb.x, xb.y},
                             {xb.z, xb.w, xc.x}, {xc.y, xc.z, xc.w}};
            float Y[4][3] = {{ya.x, ya.y, ya.z}, {ya.w, yb.x, yb.y},
                             {yb.z, yb.w, yc.x}, {yc.y, yc.z, yc.w}};
#pragma unroll
            for (int p = 0; p < 4; p++) {
#pragma unroll
                for (int j = 0; j < 3; j++) {
                    a[j]     += (double)X[p][j];
                    a[3 + j] += (double)Y[p][j];
                }
#pragma unroll
                for (int o = 0; o < 3; o++)
#pragma unroll
                    for (int i = 0; i < 3; i++)
                        a[6 + o * 3 + i] += (double)Y[p][o] * (double)X[p][i];
            }
        }
#pragma unroll
        for (int i = 0; i < 15; i++) {
            double v = a[i];
            for (int off = 16; off; off >>= 1)
                v += __shfl_down_sync(0xffffffffu, v, off);
            a[i] = v;
        }
        __shared__ double shx[NTHR / 32][15];
        if (lane == 0) {
#pragma unroll
            for (int i = 0; i < 15; i++) shx[warp][i] = a[i];
        }
        __syncthreads();
        if (tid == 0) {
#pragma unroll
            for (int i = 0; i < 15; i++) {
                double t = 0.0;
#pragma unroll
                for (int wp = 0; wp < NTHR / 32; wp++) t += shx[wp][i];
                ex[i] = t;
            }
        }
        __syncthreads();
    }

    if (tid != 0) return;

    // ---------------- Phase 3: serial 3x3 solve (thread 0) ----------------
    const double EPSF = 1.1920928955078125e-07;  // float32 eps

    bool nep = (s_nep != 0);

    double W = sums[1];
    double Sx[3], Sy[3], M[9];
#pragma unroll
    for (int j = 0; j < 3; j++) { Sx[j] = sums[2 + j]; Sy[j] = sums[5 + j]; }
#pragma unroll
    for (int j = 0; j < 9; j++) M[j] = sums[8 + j];

    if (nep) {
        W += EPSF * (double)Nf;
#pragma unroll
        for (int j = 0; j < 3; j++) {
            Sx[j] += EPSF * ex[j];
            Sy[j] += EPSF * ex[3 + j];
        }
#pragma unroll
        for (int j = 0; j < 9; j++) M[j] += EPSF * ex[6 + j];
    }

    // fast double reciprocal: fp32 seed + 2 Newton steps
    double invW = (double)__fdividef(1.0f, (float)W);
    invW = invW * (2.0 - W * invW);
    invW = invW * (2.0 - W * invW);

    double mxd[3], myd[3];
#pragma unroll
    for (int j = 0; j < 3; j++) { mxd[j] = Sx[j] * invW; myd[j] = Sy[j] * invW; }

    float A[3][3], mx[3], my[3];
#pragma unroll
    for (int o = 0; o < 3; o++) {
        my[o] = (float)myd[o];
        mx[o] = (float)mxd[o];
#pragma unroll
        for (int i = 0; i < 3; i++)
            A[o][i] = (float)(M[o * 3 + i] * invW - myd[o] * mxd[i]);
    }

    // S = A^T A
    float S[3][3];
#pragma unroll
    for (int i = 0; i < 3; i++)
#pragma unroll
        for (int j = 0; j < 3; j++) {
            float a = 0.0f;
#pragma unroll
            for (int o = 0; o < 3; o++) a = fmaf(A[o][i], A[o][j], a);
            S[i][j] = a;
        }

    // Jacobi eigendecomposition: 5 unrolled branchless sweeps
    float V[3][3] = {{1, 0, 0}, {0, 1, 0}, {0, 0, 1}};
#pragma unroll
    for (int sweep = 0; sweep < 5; sweep++) {
        jrot<0, 1>(S, V);
        jrot<0, 2>(S, V);
        jrot<1, 2>(S, V);
    }

    float d[3] = {S[0][0], S[1][1], S[2][2]};
    int idx[3] = {0, 1, 2};
    for (int a = 0; a < 2; a++)
        for (int b = 0; b < 2 - a; b++)
            if (d[idx[b]] < d[idx[b + 1]]) { int tmp = idx[b]; idx[b] = idx[b + 1]; idx[b + 1] = tmp; }

    float Vs[3][3], sig[3];
#pragma unroll
    for (int cI = 0; cI < 3; cI++) {
        float dv = d[idx[cI]];
        sig[cI] = (dv > 0.0f) ? dv * rsqrtf(dv) : 0.0f;   // sqrt(dv)
#pragma unroll
        for (int r = 0; r < 3; r++) Vs[r][cI] = V[r][idx[cI]];
    }

    float sigmax = sig[0];
    float tiny = sigmax * 1e-6f;

    float U[3][3];
#pragma unroll 1
    for (int cI = 0; cI < 3; cI++) {
        float Av[3];
#pragma unroll
        for (int r = 0; r < 3; r++)
            Av[r] = fmaf(A[r][0], Vs[0][cI],
                    fmaf(A[r][1], Vs[1][cI], A[r][2] * Vs[2][cI]));
        if (sig[cI] > tiny && sig[cI] > 0.0f) {
            float inv = __fdividef(1.0f, sig[cI]);
#pragma unroll
            for (int r = 0; r < 3; r++) U[r][cI] = Av[r] * inv;
        } else if (cI == 0) {
            U[0][0] = 1.0f; U[1][0] = 0.0f; U[2][0] = 0.0f;
        } else if (cI == 1) {
            float e[3] = {0.0f, 0.0f, 0.0f};
            e[(fabsf(U[0][0]) < 0.9f) ? 0 : 1] = 1.0f;
            float dot = e[0] * U[0][0] + e[1] * U[1][0] + e[2] * U[2][0];
            float v0 = e[0] - dot * U[0][0], v1 = e[1] - dot * U[1][0], v2 = e[2] - dot * U[2][0];
            float inv = rsqrtf(v0 * v0 + v1 * v1 + v2 * v2);
            U[0][1] = v0 * inv; U[1][1] = v1 * inv; U[2][1] = v2 * inv;
        } else {
            U[0][2] = U[1][0] * U[2][1] - U[2][0] * U[1][1];
            U[1][2] = U[2][0] * U[0][1] - U[0][0] * U[2][1];
            U[2][2] = U[0][0] * U[1][1] - U[1][0] * U[0][1];
        }
    }

    float tol = sigmax * 3.0f * (float)EPSF;
    int rank = 0;
#pragma unroll
    for (int i = 0; i < 3; i++) if (sig[i] > tol) rank++;

    float det_S = det3f(A);
    float det_mul = det3f(U) * det3f(Vs);

    float sign_full = (det_S < 0.0f) ? -1.0f : 1.0f;
    float sign_def = (fabsf(det_mul + 1.0f) <= 1.00001e-5f) ? -1.0f : 1.0f;
    float s = (rank > 2) ? sign_full : sign_def;

    float R[3][3];
#pragma unroll
    for (int o = 0; o < 3; o++)
#pragma unroll
        for (int i = 0; i < 3; i++)
            R[o][i] = fmaf(U[o][0], Vs[i][0],
                      fmaf(U[o][1], Vs[i][1], s * U[o][2] * Vs[i][2]));

    float tvec[3];
#pragma unroll
    for (int o = 0; o < 3; o++)
        tvec[o] = my[o] - fmaf(R[o][0], mx[0], fmaf(R[o][1], mx[1], R[o][2] * mx[2]));

    float Tm[16];
#pragma unroll
    for (int r = 0; r < 3; r++) {
        Tm[r * 4 + 0] = R[r][0];
        Tm[r * 4 + 1] = R[r][1];
        Tm[r * 4 + 2] = R[r][2];
        Tm[r * 4 + 3] = tvec[r];
    }
    Tm[12] = 0.0f; Tm[13] = 0.0f; Tm[14] = 0.0f; Tm[15] = 1.0f;

    int lim = (out_size < 16) ? out_size : 16;
    for (int i = 0; i < lim; i++) out[i] = Tm[i];
    float flag = nep ? 1.0f : 0.0f;
    for (int i = 16; i < out_size; i++) out[i] = flag;
}

extern "C" void kernel_launch(void* const* d_in, const int* in_sizes, int n_in,
                              void* d_out, int out_size)
{
    const float* x = (const float*)d_in[0];   // cloud_t0 (1, N, 3)
    const float* y = (const float*)d_in[1];   // cloud_t1 (1, N, 3)
    const float* w = (const float*)d_in[2];   // weights  (1, N)
    int N  = in_sizes[2];
    int n4 = N >> 2;  // N = 4194304, multiple of 4

    kabsch_fused_kernel<<<NBLK, NTHR>>>(
        (const float4*)x, (const float4*)y, (const float4*)w, n4,
        (float*)d_out, out_size, (float)N);
}

// round 16
// speedup vs baseline: 1.0772x; 1.0772x over previous
#include <cuda_runtime.h>
#include <math.h>

// ---------------------------------------------------------------------------
// Weighted Kabsch: standalone streaming reduce (32 channels — the tail-free
// kernel is the ONLY variant that streams at ~5.9TB/s; every fused version
// drops to ~3.7TB/s) + separate finalize. NBLK=296 (2 blocks/SM) keeps HBM
// saturated while cutting the finalize's partial-rows 4x.
// Channels (32):
//   0      : count(w > 0)
//   1      : sum w
//   2..4   : sum w*x
//   5..7   : sum w*y
//   8..16  : sum w*y_o*x_i   (row-major o*3+i)
//   17..19 : sum x
//   20..22 : sum y
//   23..31 : sum y_o*x_i
// ---------------------------------------------------------------------------

#define NBLK 296    // 148 SMs * 2
#define NTHR 256
#define NCH  32

__device__ float g_part[NBLK * NCH];

__global__ __launch_bounds__(NTHR) void kabsch_reduce_kernel(
    const float4* __restrict__ x4, const float4* __restrict__ y4,
    const float4* __restrict__ w4, int n4)
{
    float acc[NCH];
#pragma unroll
    for (int i = 0; i < NCH; i++) acc[i] = 0.0f;

    int stride = gridDim.x * blockDim.x;
    for (int g = blockIdx.x * blockDim.x + threadIdx.x; g < n4; g += stride) {
        float4 xa = x4[g * 3 + 0];
        float4 xb = x4[g * 3 + 1];
        float4 xc = x4[g * 3 + 2];
        float4 ya = y4[g * 3 + 0];
        float4 yb = y4[g * 3 + 1];
        float4 yc = y4[g * 3 + 2];
        float4 ww = w4[g];

        float X[4][3] = {{xa.x, xa.y, xa.z}, {xa.w, xb.x, xb.y},
                         {xb.z, xb.w, xc.x}, {xc.y, xc.z, xc.w}};
        float Y[4][3] = {{ya.x, ya.y, ya.z}, {ya.w, yb.x, yb.y},
                         {yb.z, yb.w, yc.x}, {yc.y, yc.z, yc.w}};
        float Wp[4] = {ww.x, ww.y, ww.z, ww.w};

#pragma unroll
        for (int p = 0; p < 4; p++) {
            float w = Wp[p];
            acc[0] += (w > 0.0f) ? 1.0f : 0.0f;
            acc[1] += w;
            float wy[3];
#pragma unroll
            for (int j = 0; j < 3; j++) {
                acc[2 + j]   = fmaf(w, X[p][j], acc[2 + j]);
                wy[j]        = w * Y[p][j];
                acc[5 + j]  += wy[j];
                acc[17 + j] += X[p][j];
                acc[20 + j] += Y[p][j];
            }
#pragma unroll
            for (int o = 0; o < 3; o++) {
#pragma unroll
                for (int i = 0; i < 3; i++) {
                    acc[8 + o * 3 + i]  = fmaf(wy[o],   X[p][i], acc[8 + o * 3 + i]);
                    acc[23 + o * 3 + i] = fmaf(Y[p][o], X[p][i], acc[23 + o * 3 + i]);
                }
            }
        }
    }

    // warp-level tree reduction on each channel
#pragma unroll
    for (int i = 0; i < NCH; i++) {
        float v = acc[i];
        for (int off = 16; off; off >>= 1)
            v += __shfl_down_sync(0xffffffffu, v, off);
        acc[i] = v;
    }

    __shared__ float sh[NTHR / 32][NCH];
    int lane = threadIdx.x & 31;
    int warp = threadIdx.x >> 5;
    if (lane == 0) {
#pragma unroll
        for (int i = 0; i < NCH; i++) sh[warp][i] = acc[i];
    }
    __syncthreads();

    if (threadIdx.x < NCH) {
        float v = 0.0f;
#pragma unroll
        for (int wp = 0; wp < NTHR / 32; wp++) v += sh[wp][threadIdx.x];
        g_part[blockIdx.x * NCH + threadIdx.x] = v;
    }
}

// ---------------------------------------------------------------------------
// Finalize: fp32 partial reduction over 296 rows, tiny fp64 combine/preamble,
// fast fp32 3x3 Jacobi SVD, emit T + flag.
// ---------------------------------------------------------------------------

__device__ __forceinline__ float det3f(const float M[3][3]) {
    return M[0][0] * (M[1][1] * M[2][2] - M[1][2] * M[2][1])
         - M[0][1] * (M[1][0] * M[2][2] - M[1][2] * M[2][0])
         + M[0][2] * (M[1][0] * M[2][1] - M[1][1] * M[2][0]);
}

template<int P, int Q>
__device__ __forceinline__ void jrot(float S[3][3], float V[3][3]) {
    float apq = S[P][Q];
    float d2 = 2.0f * apq;
    d2 = (d2 == 0.0f) ? 1e-37f : d2;
    float tau = __fdividef(S[Q][Q] - S[P][P], d2);
    tau = fminf(fmaxf(tau, -1e18f), 1e18f);
    float z  = fmaf(tau, tau, 1.0f);
    float sq = z * rsqrtf(z);                    // sqrt(z), z >= 1
    float t  = __fdividef(1.0f, fabsf(tau) + sq);
    t = copysignf(t, tau);
    float cc = rsqrtf(fmaf(t, t, 1.0f));
    float ss = t * cc;
#pragma unroll
    for (int kk = 0; kk < 3; kk++) {
        float skp = S[kk][P], skq = S[kk][Q];
        S[kk][P] = fmaf(cc, skp, -ss * skq);
        S[kk][Q] = fmaf(ss, skp,  cc * skq);
    }
#pragma unroll
    for (int kk = 0; kk < 3; kk++) {
        float spk = S[P][kk], sqk = S[Q][kk];
        S[P][kk] = fmaf(cc, spk, -ss * sqk);
        S[Q][kk] = fmaf(ss, spk,  cc * sqk);
    }
#pragma unroll
    for (int kk = 0; kk < 3; kk++) {
        float vkp = V[kk][P], vkq = V[kk][Q];
        V[kk][P] = fmaf(cc, vkp, -ss * vkq);
        V[kk][Q] = fmaf(ss, vkp,  cc * vkq);
    }
}

__global__ __launch_bounds__(256) void kabsch_finalize_kernel(
    float* __restrict__ out, int out_size, float Nf)
{
    // 256 threads: channel = tid&31, chunk = tid>>5 (8 chunks of 37 rows)
    __shared__ float  s2[8][NCH];
    __shared__ double sums[NCH];

    int tid = threadIdx.x;
    int c = tid & 31;
    int k = tid >> 5;
    const int per = NBLK / 8;  // 37

    {
        const float* base = &g_part[((k * per) << 5) + c];
        float a0 = 0.0f, a1 = 0.0f, a2 = 0.0f, a3 = 0.0f;
#pragma unroll
        for (int j = 0; j < per / 4; j++) {       // 9 rounds of 4
            a0 += base[((4 * j + 0) << 5)];
            a1 += base[((4 * j + 1) << 5)];
            a2 += base[((4 * j + 2) << 5)];
            a3 += base[((4 * j + 3) << 5)];
        }
        a0 += base[36 << 5];                      // 37th row
        s2[k][c] = (a0 + a1) + (a2 + a3);
    }
    __syncthreads();

    if (tid < NCH) {
        double t = 0.0;
#pragma unroll
        for (int kk = 0; kk < 8; kk++) t += (double)s2[kk][tid];
        sums[tid] = t;
    }
    __syncthreads();

    if (tid != 0) return;

    const double EPSF = 1.1920928955078125e-07;  // float32 eps

    bool nep = sums[0] < 2.5;                    // count_nonzero < 3

    double W = sums[1];
    double Sx[3], Sy[3], M[9];
#pragma unroll
    for (int j = 0; j < 3; j++) { Sx[j] = sums[2 + j]; Sy[j] = sums[5 + j]; }
#pragma unroll
    for (int j = 0; j < 9; j++) M[j] = sums[8 + j];

    if (nep) {
        W += EPSF * (double)Nf;
#pragma unroll
        for (int j = 0; j < 3; j++) {
            Sx[j] += EPSF * sums[17 + j];
            Sy[j] += EPSF * sums[20 + j];
        }
#pragma unroll
        for (int j = 0; j < 9; j++) M[j] += EPSF * sums[23 + j];
    }

    // fast double reciprocal: fp32 seed + 2 Newton steps
    double invW = (double)__fdividef(1.0f, (float)W);
    invW = invW * (2.0 - W * invW);
    invW = invW * (2.0 - W * invW);

    double mxd[3], myd[3];
#pragma unroll
    for (int j = 0; j < 3; j++) { mxd[j] = Sx[j] * invW; myd[j] = Sy[j] * invW; }

    float A[3][3], mx[3], my[3];
#pragma unroll
    for (int o = 0; o < 3; o++) {
        my[o] = (float)myd[o];
        mx[o] = (float)mxd[o];
#pragma unroll
        for (int i = 0; i < 3; i++)
            A[o][i] = (float)(M[o * 3 + i] * invW - myd[o] * mxd[i]);
    }

    // S = A^T A
    float S[3][3];
#pragma unroll
    for (int i = 0; i < 3; i++)
#pragma unroll
        for (int j = 0; j < 3; j++) {
            float a = 0.0f;
#pragma unroll
            for (int o = 0; o < 3; o++) a = fmaf(A[o][i], A[o][j], a);
            S[i][j] = a;
        }

    // Jacobi eigendecomposition: 5 unrolled branchless sweeps
    float V[3][3] = {{1, 0, 0}, {0, 1, 0}, {0, 0, 1}};
#pragma unroll
    for (int sweep = 0; sweep < 5; sweep++) {
        jrot<0, 1>(S, V);
        jrot<0, 2>(S, V);
        jrot<1, 2>(S, V);
    }

    float d[3] = {S[0][0], S[1][1], S[2][2]};
    int idx[3] = {0, 1, 2};
    for (int a = 0; a < 2; a++)
        for (int b = 0; b < 2 - a; b++)
            if (d[idx[b]] < d[idx[b + 1]]) { int tmp = idx[b]; idx[b] = idx[b + 1]; idx[b + 1] = tmp; }

    float Vs[3][3], sig[3];
#pragma unroll
    for (int cI = 0; cI < 3; cI++) {
        float dv = d[idx[cI]];
        sig[cI] = (dv > 0.0f) ? dv * rsqrtf(dv) : 0.0f;   // sqrt(dv)
#pragma unroll
        for (int r = 0; r < 3; r++) Vs[r][cI] = V[r][idx[cI]];
    }

    float sigmax = sig[0];
    float tiny = sigmax * 1e-6f;

    float U[3][3];
#pragma unroll 1
    for (int cI = 0; cI < 3; cI++) {
        float Av[3];
#pragma unroll
        for (int r = 0; r < 3; r++)
            Av[r] = fmaf(A[r][0], Vs[0][cI],
                    fmaf(A[r][1], Vs[1][cI], A[r][2] * Vs[2][cI]));
        if (sig[cI] > tiny && sig[cI] > 0.0f) {
            float inv = __fdividef(1.0f, sig[cI]);
#pragma unroll
            for (int r = 0; r < 3; r++) U[r][cI] = Av[r] * inv;
        } else if (cI == 0) {
            U[0][0] = 1.0f; U[1][0] = 0.0f; U[2][0] = 0.0f;
        } else if (cI == 1) {
            float e[3] = {0.0f, 0.0f, 0.0f};
            e[(fabsf(U[0][0]) < 0.9f) ? 0 : 1] = 1.0f;
            float dot = e[0] * U[0][0] + e[1] * U[1][0] + e[2] * U[2][0];
            float v0 = e[0] - dot * U[0][0], v1 = e[1] - dot * U[1][0], v2 = e[2] - dot * U[2][0];
            float inv = rsqrtf(v0 * v0 + v1 * v1 + v2 * v2);
            U[0][1] = v0 * inv; U[1][1] = v1 * inv; U[2][1] = v2 * inv;
        } else {
            U[0][2] = U[1][0] * U[2][1] - U[2][0] * U[1][1];
            U[1][2] = U[2][0] * U[0][1] - U[0][0] * U[2][1];
            U[2][2] = U[0][0] * U[1][1] - U[1][0] * U[0][1];
        }
    }

    float tol = sigmax * 3.0f * (float)EPSF;
    int rank = 0;
#pragma unroll
    for (int i = 0; i < 3; i++) if (sig[i] > tol) rank++;

    float det_S = det3f(A);
    float det_mul = det3f(U) * det3f(Vs);

    float sign_full = (det_S < 0.0f) ? -1.0f : 1.0f;
    float sign_def = (fabsf(det_mul + 1.0f) <= 1.00001e-5f) ? -1.0f : 1.0f;
    float s = (rank > 2) ? sign_full : sign_def;

    float R[3][3];
#pragma unroll
    for (int o = 0; o < 3; o++)
#pragma unroll
        for (int i = 0; i < 3; i++)
            R[o][i] = fmaf(U[o][0], Vs[i][0],
                      fmaf(U[o][1], Vs[i][1], s * U[o][2] * Vs[i][2]));

    float tvec[3];
#pragma unroll
    for (int o = 0; o < 3; o++)
        tvec[o] = my[o] - fmaf(R[o][0], mx[0], fmaf(R[o][1], mx[1], R[o][2] * mx[2]));

    float Tm[16];
#pragma unroll
    for (int r = 0; r < 3; r++) {
        Tm[r * 4 + 0] = R[r][0];
        Tm[r * 4 + 1] = R[r][1];
        Tm[r * 4 + 2] = R[r][2];
        Tm[r * 4 + 3] = tvec[r];
    }
    Tm[12] = 0.0f; Tm[13] = 0.0f; Tm[14] = 0.0f; Tm[15] = 1.0f;

    int lim = (out_size < 16) ? out_size : 16;
    for (int i = 0; i < lim; i++) out[i] = Tm[i];
    float flag = nep ? 1.0f : 0.0f;
    for (int i = 16; i < out_size; i++) out[i] = flag;
}

extern "C" void kernel_launch(void* const* d_in, const int* in_sizes, int n_in,
                              void* d_out, int out_size)
{
    const float* x = (const float*)d_in[0];   // cloud_t0 (1, N, 3)
    const float* y = (const float*)d_in[1];   // cloud_t1 (1, N, 3)
    const float* w = (const float*)d_in[2];   // weights  (1, N)
    int N  = in_sizes[2];
    int n4 = N >> 2;  // N = 4194304, multiple of 4

    kabsch_reduce_kernel<<<NBLK, NTHR>>>(
        (const float4*)x, (const float4*)y, (const float4*)w, n4);
    kabsch_finalize_kernel<<<1, 256>>>((float*)d_out, out_size, (float)N);
}

// round 17
// speedup vs baseline: 1.1623x; 1.0789x over previous
#include <cuda_runtime.h>
#include <math.h>

// ---------------------------------------------------------------------------
// Weighted Kabsch: standalone streaming reduce (32 channels, NBLK=1184 — the
// proven-fastest config, ~5.9TB/s; fused variants drop to ~3.7TB/s) +
// finalize with 1024 threads: 32 chunks x 37 rows cuts the dependent L2-load
// chain 4x, and the cross-chunk combine is fp32-ILP instead of a serial fp64
// chain. FP64 survives only in the ~30-op preamble.
// Channels (32):
//   0      : count(w > 0)
//   1      : sum w
//   2..4   : sum w*x
//   5..7   : sum w*y
//   8..16  : sum w*y_o*x_i   (row-major o*3+i)
//   17..19 : sum x
//   20..22 : sum y
//   23..31 : sum y_o*x_i
// ---------------------------------------------------------------------------

#define NBLK 1184   // 148 SMs * 8
#define NTHR 256
#define NCH  32

__device__ float g_part[NBLK * NCH];

__global__ __launch_bounds__(NTHR) void kabsch_reduce_kernel(
    const float4* __restrict__ x4, const float4* __restrict__ y4,
    const float4* __restrict__ w4, int n4)
{
    float acc[NCH];
#pragma unroll
    for (int i = 0; i < NCH; i++) acc[i] = 0.0f;

    int stride = gridDim.x * blockDim.x;
    for (int g = blockIdx.x * blockDim.x + threadIdx.x; g < n4; g += stride) {
        float4 xa = x4[g * 3 + 0];
        float4 xb = x4[g * 3 + 1];
        float4 xc = x4[g * 3 + 2];
        float4 ya = y4[g * 3 + 0];
        float4 yb = y4[g * 3 + 1];
        float4 yc = y4[g * 3 + 2];
        float4 ww = w4[g];

        float X[4][3] = {{xa.x, xa.y, xa.z}, {xa.w, xb.x, xb.y},
                         {xb.z, xb.w, xc.x}, {xc.y, xc.z, xc.w}};
        float Y[4][3] = {{ya.x, ya.y, ya.z}, {ya.w, yb.x, yb.y},
                         {yb.z, yb.w, yc.x}, {yc.y, yc.z, yc.w}};
        float Wp[4] = {ww.x, ww.y, ww.z, ww.w};

#pragma unroll
        for (int p = 0; p < 4; p++) {
            float w = Wp[p];
            acc[0] += (w > 0.0f) ? 1.0f : 0.0f;
            acc[1] += w;
            float wy[3];
#pragma unroll
            for (int j = 0; j < 3; j++) {
                acc[2 + j]   = fmaf(w, X[p][j], acc[2 + j]);
                wy[j]        = w * Y[p][j];
                acc[5 + j]  += wy[j];
                acc[17 + j] += X[p][j];
                acc[20 + j] += Y[p][j];
            }
#pragma unroll
            for (int o = 0; o < 3; o++) {
#pragma unroll
                for (int i = 0; i < 3; i++) {
                    acc[8 + o * 3 + i]  = fmaf(wy[o],   X[p][i], acc[8 + o * 3 + i]);
                    acc[23 + o * 3 + i] = fmaf(Y[p][o], X[p][i], acc[23 + o * 3 + i]);
                }
            }
        }
    }

    // warp-level tree reduction on each channel
#pragma unroll
    for (int i = 0; i < NCH; i++) {
        float v = acc[i];
        for (int off = 16; off; off >>= 1)
            v += __shfl_down_sync(0xffffffffu, v, off);
        acc[i] = v;
    }

    __shared__ float sh[NTHR / 32][NCH];
    int lane = threadIdx.x & 31;
    int warp = threadIdx.x >> 5;
    if (lane == 0) {
#pragma unroll
        for (int i = 0; i < NCH; i++) sh[warp][i] = acc[i];
    }
    __syncthreads();

    if (threadIdx.x < NCH) {
        float v = 0.0f;
#pragma unroll
        for (int wp = 0; wp < NTHR / 32; wp++) v += sh[wp][threadIdx.x];
        g_part[blockIdx.x * NCH + threadIdx.x] = v;
    }
}

// ---------------------------------------------------------------------------
// Finalize (1024 threads): fp32 partial reduction over 1184 rows with a
// short dependent-load chain, fp32-ILP cross-chunk combine, fp64 preamble,
// fast fp32 3x3 Jacobi SVD, emit T + flag.
// ---------------------------------------------------------------------------

__device__ __forceinline__ float det3f(const float M[3][3]) {
    return M[0][0] * (M[1][1] * M[2][2] - M[1][2] * M[2][1])
         - M[0][1] * (M[1][0] * M[2][2] - M[1][2] * M[2][0])
         + M[0][2] * (M[1][0] * M[2][1] - M[1][1] * M[2][0]);
}

template<int P, int Q>
__device__ __forceinline__ void jrot(float S[3][3], float V[3][3]) {
    float apq = S[P][Q];
    float d2 = 2.0f * apq;
    d2 = (d2 == 0.0f) ? 1e-37f : d2;
    float tau = __fdividef(S[Q][Q] - S[P][P], d2);
    tau = fminf(fmaxf(tau, -1e18f), 1e18f);
    float z  = fmaf(tau, tau, 1.0f);
    float sq = z * rsqrtf(z);                    // sqrt(z), z >= 1
    float t  = __fdividef(1.0f, fabsf(tau) + sq);
    t = copysignf(t, tau);
    float cc = rsqrtf(fmaf(t, t, 1.0f));
    float ss = t * cc;
#pragma unroll
    for (int kk = 0; kk < 3; kk++) {
        float skp = S[kk][P], skq = S[kk][Q];
        S[kk][P] = fmaf(cc, skp, -ss * skq);
        S[kk][Q] = fmaf(ss, skp,  cc * skq);
    }
#pragma unroll
    for (int kk = 0; kk < 3; kk++) {
        float spk = S[P][kk], sqk = S[Q][kk];
        S[P][kk] = fmaf(cc, spk, -ss * sqk);
        S[Q][kk] = fmaf(ss, spk,  cc * sqk);
    }
#pragma unroll
    for (int kk = 0; kk < 3; kk++) {
        float vkp = V[kk][P], vkq = V[kk][Q];
        V[kk][P] = fmaf(cc, vkp, -ss * vkq);
        V[kk][Q] = fmaf(ss, vkp,  cc * vkq);
    }
}

__global__ __launch_bounds__(1024) void kabsch_finalize_kernel(
    float* __restrict__ out, int out_size, float Nf)
{
    // 1024 threads: channel = tid&31, chunk = tid>>5 (32 chunks of 37 rows)
    __shared__ float  s2[32][NCH];
    __shared__ double sums[NCH];

    int tid = threadIdx.x;
    int c = tid & 31;
    int k = tid >> 5;
    const int per = NBLK / 32;  // 37 = 4*9 + 1

    {
        const float* base = &g_part[((k * per) << 5) + c];
        float a0 = 0.0f, a1 = 0.0f, a2 = 0.0f, a3 = 0.0f;
#pragma unroll
        for (int j = 0; j < per / 4; j++) {       // 9 rounds of 4
            a0 += base[((4 * j + 0) << 5)];
            a1 += base[((4 * j + 1) << 5)];
            a2 += base[((4 * j + 2) << 5)];
            a3 += base[((4 * j + 3) << 5)];
        }
        a0 += base[36 << 5];                      // 37th row
        s2[k][c] = (a0 + a1) + (a2 + a3);
    }
    __syncthreads();

    if (tid < NCH) {
        // fp32 ILP combine of 32 chunk sums, then one conversion to double
        float b0 = 0.0f, b1 = 0.0f, b2 = 0.0f, b3 = 0.0f;
#pragma unroll
        for (int kk = 0; kk < 8; kk++) {
            b0 += s2[4 * kk + 0][tid];
            b1 += s2[4 * kk + 1][tid];
            b2 += s2[4 * kk + 2][tid];
            b3 += s2[4 * kk + 3][tid];
        }
        sums[tid] = (double)((b0 + b1) + (b2 + b3));
    }
    __syncthreads();

    if (tid != 0) return;

    const double EPSF = 1.1920928955078125e-07;  // float32 eps

    bool nep = sums[0] < 2.5;                    // count_nonzero < 3

    double W = sums[1];
    double Sx[3], Sy[3], M[9];
#pragma unroll
    for (int j = 0; j < 3; j++) { Sx[j] = sums[2 + j]; Sy[j] = sums[5 + j]; }
#pragma unroll
    for (int j = 0; j < 9; j++) M[j] = sums[8 + j];

    if (nep) {
        W += EPSF * (double)Nf;
#pragma unroll
        for (int j = 0; j < 3; j++) {
            Sx[j] += EPSF * sums[17 + j];
            Sy[j] += EPSF * sums[20 + j];
        }
#pragma unroll
        for (int j = 0; j < 9; j++) M[j] += EPSF * sums[23 + j];
    }

    // fast double reciprocal: fp32 seed + 2 Newton steps
    double invW = (double)__fdividef(1.0f, (float)W);
    invW = invW * (2.0 - W * invW);
    invW = invW * (2.0 - W * invW);

    double mxd[3], myd[3];
#pragma unroll
    for (int j = 0; j < 3; j++) { mxd[j] = Sx[j] * invW; myd[j] = Sy[j] * invW; }

    float A[3][3], mx[3], my[3];
#pragma unroll
    for (int o = 0; o < 3; o++) {
        my[o] = (float)myd[o];
        mx[o] = (float)mxd[o];
#pragma unroll
        for (int i = 0; i < 3; i++)
            A[o][i] = (float)(M[o * 3 + i] * invW - myd[o] * mxd[i]);
    }

    // S = A^T A
    float S[3][3];
#pragma unroll
    for (int i = 0; i < 3; i++)
#pragma unroll
        for (int j = 0; j < 3; j++) {
            float a = 0.0f;
#pragma unroll
            for (int o = 0; o < 3; o++) a = fmaf(A[o][i], A[o][j], a);
            S[i][j] = a;
        }

    // Jacobi eigendecomposition: 5 unrolled branchless sweeps
    float V[3][3] = {{1, 0, 0}, {0, 1, 0}, {0, 0, 1}};
#pragma unroll
    for (int sweep = 0; sweep < 5; sweep++) {
        jrot<0, 1>(S, V);
        jrot<0, 2>(S, V);
        jrot<1, 2>(S, V);
    }

    float d[3] = {S[0][0], S[1][1], S[2][2]};
    int idx[3] = {0, 1, 2};
    for (int a = 0; a < 2; a++)
        for (int b = 0; b < 2 - a; b++)
            if (d[idx[b]] < d[idx[b + 1]]) { int tmp = idx[b]; idx[b] = idx[b + 1]; idx[b + 1] = tmp; }

    float Vs[3][3], sig[3];
#pragma unroll
    for (int cI = 0; cI < 3; cI++) {
        float dv = d[idx[cI]];
        sig[cI] = (dv > 0.0f) ? dv * rsqrtf(dv) : 0.0f;   // sqrt(dv)
#pragma unroll
        for (int r = 0; r < 3; r++) Vs[r][cI] = V[r][idx[cI]];
    }

    float sigmax = sig[0];
    float tiny = sigmax * 1e-6f;

    float U[3][3];
#pragma unroll 1
    for (int cI = 0; cI < 3; cI++) {
        float Av[3];
#pragma unroll
        for (int r = 0; r < 3; r++)
            Av[r] = fmaf(A[r][0], Vs[0][cI],
                    fmaf(A[r][1], Vs[1][cI], A[r][2] * Vs[2][cI]));
        if (sig[cI] > tiny && sig[cI] > 0.0f) {
            float inv = __fdividef(1.0f, sig[cI]);
#pragma unroll
            for (int r = 0; r < 3; r++) U[r][cI] = Av[r] * inv;
        } else if (cI == 0) {
            U[0][0] = 1.0f; U[1][0] = 0.0f; U[2][0] = 0.0f;
        } else if (cI == 1) {
            float e[3] = {0.0f, 0.0f, 0.0f};
            e[(fabsf(U[0][0]) < 0.9f) ? 0 : 1] = 1.0f;
            float dot = e[0] * U[0][0] + e[1] * U[1][0] + e[2] * U[2][0];
            float v0 = e[0] - dot * U[0][0], v1 = e[1] - dot * U[1][0], v2 = e[2] - dot * U[2][0];
            float inv = rsqrtf(v0 * v0 + v1 * v1 + v2 * v2);
            U[0][1] = v0 * inv; U[1][1] = v1 * inv; U[2][1] = v2 * inv;
        } else {
            U[0][2] = U[1][0] * U[2][1] - U[2][0] * U[1][1];
            U[1][2] = U[2][0] * U[0][1] - U[0][0] * U[2][1];
            U[2][2] = U[0][0] * U[1][1] - U[1][0] * U[0][1];
        }
    }

    float tol = sigmax * 3.0f * (float)EPSF;
    int rank = 0;
#pragma unroll
    for (int i = 0; i < 3; i++) if (sig[i] > tol) rank++;

    float det_S = det3f(A);
    float det_mul = det3f(U) * det3f(Vs);

    float sign_full = (det_S < 0.0f) ? -1.0f : 1.0f;
    float sign_def = (fabsf(det_mul + 1.0f) <= 1.00001e-5f) ? -1.0f : 1.0f;
    float s = (rank > 2) ? sign_full : sign_def;

    float R[3][3];
#pragma unroll
    for (int o = 0; o < 3; o++)
#pragma unroll
        for (int i = 0; i < 3; i++)
            R[o][i] = fmaf(U[o][0], Vs[i][0],
                      fmaf(U[o][1], Vs[i][1], s * U[o][2] * Vs[i][2]));

    float tvec[3];
#pragma unroll
    for (int o = 0; o < 3; o++)
        tvec[o] = my[o] - fmaf(R[o][0], mx[0], fmaf(R[o][1], mx[1], R[o][2] * mx[2]));

    float Tm[16];
#pragma unroll
    for (int r = 0; r < 3; r++) {
        Tm[r * 4 + 0] = R[r][0];
        Tm[r * 4 + 1] = R[r][1];
        Tm[r * 4 + 2] = R[r][2];
        Tm[r * 4 + 3] = tvec[r];
    }
    Tm[12] = 0.0f; Tm[13] = 0.0f; Tm[14] = 0.0f; Tm[15] = 1.0f;

    int lim = (out_size < 16) ? out_size : 16;
    for (int i = 0; i < lim; i++) out[i] = Tm[i];
    float flag = nep ? 1.0f : 0.0f;
    for (int i = 16; i < out_size; i++) out[i] = flag;
}

extern "C" void kernel_launch(void* const* d_in, const int* in_sizes, int n_in,
                              void* d_out, int out_size)
{
    const float* x = (const float*)d_in[0];   // cloud_t0 (1, N, 3)
    const float* y = (const float*)d_in[1];   // cloud_t1 (1, N, 3)
    const float* w = (const float*)d_in[2];   // weights  (1, N)
    int N  = in_sizes[2];
    int n4 = N >> 2;  // N = 4194304, multiple of 4

    kabsch_reduce_kernel<<<NBLK, NTHR>>>(
        (const float4*)x, (const float4*)y, (const float4*)w, n4);
    kabsch_finalize_kernel<<<1, 1024>>>((float*)d_out, out_size, (float)N);
}